// round 1
// baseline (speedup 1.0000x reference)
#include <cuda_runtime.h>

// FokkerPlanck2D step:
// f_new = max(0, f + dt * rhs), 9-point stencil with per-pixel weights:
//   center  : 1 - dt*(D0+D1)                 at (i,j)
//   (+1, 0) : dt*( 0.5*D0 - 0.5*A0)          at (i+1,j)
//   (-1, 0) : dt*( 0.5*D0 + 0.5*A0)          at (i-1,j)
//   ( 0,+1) : dt*( 0.5*D1 - 0.5*A1)          at (i,j+1)
//   ( 0,-1) : dt*( 0.5*D1 + 0.5*A1)          at (i,j-1)
//   (+1,+1) : +0.25*dt*D2                    at (i+1,j+1)
//   (+1,-1) : -0.25*dt*D2                    at (i+1,j-1)
//   (-1,+1) : -0.25*dt*D2                    at (i-1,j+1)
//   (-1,-1) : +0.25*dt*D2                    at (i-1,j-1)
// Zero (vacuum) boundaries: out-of-grid f treated as 0.

static constexpr int NXC    = 512;
static constexpr int NYC    = 512;
static constexpr int ICH    = 16;         // i-rows per block (pencil length)
static constexpr int NBATCH = 4;          // batches per block
static constexpr int TPB    = NYC / 4;    // 128 threads, float4 each -> full row

__device__ __forceinline__ void load_win6(const float* __restrict__ row, int j0,
                                          bool L, bool R, float v[6]) {
    // v[m] = row[j0 + m - 1], zero-filled outside [0, NYC)
    const float4 m4 = __ldg(reinterpret_cast<const float4*>(row + j0));
    v[0] = L ? __ldg(row + j0 - 1) : 0.0f;
    v[1] = m4.x; v[2] = m4.y; v[3] = m4.z; v[4] = m4.w;
    v[5] = R ? __ldg(row + j0 + 4) : 0.0f;
}

__global__ __launch_bounds__(TPB)
void fp2d_step_kernel(const float* __restrict__ f,
                      const float* __restrict__ A,
                      const float* __restrict__ D,
                      const float* __restrict__ dtp,
                      float* __restrict__ out) {
    const int tid = threadIdx.x;
    const int j0  = tid * 4;
    const bool L  = (tid > 0);
    const bool R  = (tid < TPB - 1);
    const int i0  = blockIdx.x * ICH;
    const long b0 = (long)blockIdx.y * NBATCH;

    const float dt  = __ldg(dtp);
    const float hdt = 0.5f  * dt;
    const float qdt = 0.25f * dt;

    const long plane = (long)NXC * NYC;
    const float* A0 = A;
    const float* A1 = A + plane;
    const float* D0 = D;
    const float* D1 = D + plane;
    const float* D2 = D + 2 * plane;

    // f windows: [m] = f[row][j0+m-1], rotated along i
    float fm[NBATCH][6], fc[NBATCH][6], fp[NBATCH][6];
    // coefficient pipelines
    float wxm_use[4], wxm_nxt[4];   // (-1,0) weight: computed at row r, used when r == i-1
    float wdm[6], wdmid[6];         // diag weights: computed at row r, used when r == i-1
    float cc[4], cyp[4], cym[4];    // center-row weights for current output row
    float ncc[4], ncyp[4], ncym[4]; // staged for next output row

    // ---------------- prologue: row i0-1 ----------------
    {
        const int r = i0 - 1;
        if (r >= 0) {
            const float* frow = f + (long)r * NYC;
            #pragma unroll
            for (int b = 0; b < NBATCH; ++b)
                load_win6(frow + (b0 + b) * plane, j0, L, R, fm[b]);
            const float4 a0 = __ldg(reinterpret_cast<const float4*>(A0 + (long)r * NYC + j0));
            const float4 d0 = __ldg(reinterpret_cast<const float4*>(D0 + (long)r * NYC + j0));
            wxm_use[0] = hdt * (d0.x + a0.x);
            wxm_use[1] = hdt * (d0.y + a0.y);
            wxm_use[2] = hdt * (d0.z + a0.z);
            wxm_use[3] = hdt * (d0.w + a0.w);
            float d2w[6];
            load_win6(D2 + (long)r * NYC, j0, L, R, d2w);
            #pragma unroll
            for (int m = 0; m < 6; ++m) wdm[m] = qdt * d2w[m];
        } else {
            #pragma unroll
            for (int b = 0; b < NBATCH; ++b)
                #pragma unroll
                for (int m = 0; m < 6; ++m) fm[b][m] = 0.0f;
            #pragma unroll
            for (int k = 0; k < 4; ++k) wxm_use[k] = 0.0f;
            #pragma unroll
            for (int m = 0; m < 6; ++m) wdm[m] = 0.0f;
        }
    }
    // ---------------- prologue: row i0 ----------------
    {
        const int r = i0;   // always in range
        const float* frow = f + (long)r * NYC;
        #pragma unroll
        for (int b = 0; b < NBATCH; ++b)
            load_win6(frow + (b0 + b) * plane, j0, L, R, fc[b]);
        const float4 a0 = __ldg(reinterpret_cast<const float4*>(A0 + (long)r * NYC + j0));
        const float4 d0 = __ldg(reinterpret_cast<const float4*>(D0 + (long)r * NYC + j0));
        wxm_nxt[0] = hdt * (d0.x + a0.x);
        wxm_nxt[1] = hdt * (d0.y + a0.y);
        wxm_nxt[2] = hdt * (d0.z + a0.z);
        wxm_nxt[3] = hdt * (d0.w + a0.w);
        float d2w[6], d1w[6], a1w[6];
        load_win6(D2 + (long)r * NYC, j0, L, R, d2w);
        load_win6(D1 + (long)r * NYC, j0, L, R, d1w);
        load_win6(A1 + (long)r * NYC, j0, L, R, a1w);
        #pragma unroll
        for (int m = 0; m < 6; ++m) wdmid[m] = qdt * d2w[m];
        const float d0v[4] = {d0.x, d0.y, d0.z, d0.w};
        #pragma unroll
        for (int k = 0; k < 4; ++k) {
            cc[k]  = 1.0f - dt * (d0v[k] + d1w[k + 1]);
            cyp[k] = hdt * (d1w[k + 2] - a1w[k + 2]);
            cym[k] = hdt * (d1w[k]     + a1w[k]);
        }
    }

    // ---------------- main i-march ----------------
    for (int i = i0; i < i0 + ICH; ++i) {
        float wxp[4], wdp[6], wxm_new[4];
        const int r = i + 1;
        if (r < NXC) {
            const float* frow = f + (long)r * NYC;
            #pragma unroll
            for (int b = 0; b < NBATCH; ++b)
                load_win6(frow + (b0 + b) * plane, j0, L, R, fp[b]);
            const float4 a0 = __ldg(reinterpret_cast<const float4*>(A0 + (long)r * NYC + j0));
            const float4 d0 = __ldg(reinterpret_cast<const float4*>(D0 + (long)r * NYC + j0));
            wxp[0] = hdt * (d0.x - a0.x);  wxm_new[0] = hdt * (d0.x + a0.x);
            wxp[1] = hdt * (d0.y - a0.y);  wxm_new[1] = hdt * (d0.y + a0.y);
            wxp[2] = hdt * (d0.z - a0.z);  wxm_new[2] = hdt * (d0.z + a0.z);
            wxp[3] = hdt * (d0.w - a0.w);  wxm_new[3] = hdt * (d0.w + a0.w);
            float d2w[6], d1w[6], a1w[6];
            load_win6(D2 + (long)r * NYC, j0, L, R, d2w);
            load_win6(D1 + (long)r * NYC, j0, L, R, d1w);
            load_win6(A1 + (long)r * NYC, j0, L, R, a1w);
            #pragma unroll
            for (int m = 0; m < 6; ++m) wdp[m] = qdt * d2w[m];
            const float d0v[4] = {d0.x, d0.y, d0.z, d0.w};
            #pragma unroll
            for (int k = 0; k < 4; ++k) {
                ncc[k]  = 1.0f - dt * (d0v[k] + d1w[k + 1]);
                ncyp[k] = hdt * (d1w[k + 2] - a1w[k + 2]);
                ncym[k] = hdt * (d1w[k]     + a1w[k]);
            }
        } else {
            #pragma unroll
            for (int b = 0; b < NBATCH; ++b)
                #pragma unroll
                for (int m = 0; m < 6; ++m) fp[b][m] = 0.0f;
            #pragma unroll
            for (int k = 0; k < 4; ++k) { wxp[k] = 0.0f; wxm_new[k] = 0.0f;
                                          ncc[k] = 0.0f; ncyp[k] = 0.0f; ncym[k] = 0.0f; }
            #pragma unroll
            for (int m = 0; m < 6; ++m) wdp[m] = 0.0f;
        }

        // compute + store outputs for row i
        #pragma unroll
        for (int b = 0; b < NBATCH; ++b) {
            float4 res;
            float rv[4];
            #pragma unroll
            for (int k = 0; k < 4; ++k) {
                const int j = k + 1;  // window index of column j0+k
                float v = cc[k] * fc[b][j];
                v += wxp[k]     * fp[b][j];
                v += wxm_use[k] * fm[b][j];
                v += cyp[k]     * fc[b][j + 1];
                v += cym[k]     * fc[b][j - 1];
                v += wdp[k + 2] * fp[b][k + 2];
                v -= wdp[k]     * fp[b][k];
                v -= wdm[k + 2] * fm[b][k + 2];
                v += wdm[k]     * fm[b][k];
                rv[k] = fmaxf(v, 0.0f);
            }
            res.x = rv[0]; res.y = rv[1]; res.z = rv[2]; res.w = rv[3];
            *reinterpret_cast<float4*>(out + (b0 + b) * plane + (long)i * NYC + j0) = res;
        }

        // rotate pipelines
        #pragma unroll
        for (int b = 0; b < NBATCH; ++b)
            #pragma unroll
            for (int m = 0; m < 6; ++m) { fm[b][m] = fc[b][m]; fc[b][m] = fp[b][m]; }
        #pragma unroll
        for (int k = 0; k < 4; ++k) {
            wxm_use[k] = wxm_nxt[k]; wxm_nxt[k] = wxm_new[k];
            cc[k] = ncc[k]; cyp[k] = ncyp[k]; cym[k] = ncym[k];
        }
        #pragma unroll
        for (int m = 0; m < 6; ++m) { wdm[m] = wdmid[m]; wdmid[m] = wdp[m]; }
    }
}

extern "C" void kernel_launch(void* const* d_in, const int* in_sizes, int n_in,
                              void* d_out, int out_size) {
    const float* f  = (const float*)d_in[0];
    const float* A  = (const float*)d_in[1];
    const float* D  = (const float*)d_in[2];
    const float* dt = (const float*)d_in[3];
    float* out = (float*)d_out;

    const int plane = NXC * NYC;
    const int B = in_sizes[0] / plane;   // 128

    dim3 grid(NXC / ICH, B / NBATCH);    // (32, 32)
    fp2d_step_kernel<<<grid, TPB>>>(f, A, D, dt, out);
}